// round 4
// baseline (speedup 1.0000x reference)
#include <cuda_runtime.h>
#include <cuda_bf16.h>
#include <cstdint>

// Problem constants
#define BATCH 4
#define SEQ   1024
#define CDIM  2048
#define NHEAD 32
#define HDIM  64
#define QKVN  (3*CDIM)          // 6144
#define MROWS (BATCH*SEQ)       // 4096

// Scratch (device globals: allocation-free rule)
__device__ float g_qkv[(size_t)MROWS * QKVN];
__device__ float g_q[(size_t)BATCH*NHEAD*SEQ*HDIM];
__device__ float g_k[(size_t)BATCH*NHEAD*SEQ*HDIM];
__device__ float g_v[(size_t)BATCH*NHEAD*SEQ*HDIM];

typedef unsigned long long ull;

// ---------------------------------------------------------------------------
// helpers
// ---------------------------------------------------------------------------
__device__ __forceinline__ uint32_t smem_u32(const void* p) {
    uint32_t a;
    asm("{ .reg .u64 t; cvta.to.shared.u64 t, %1; cvt.u32.u64 %0, t; }" : "=r"(a) : "l"(p));
    return a;
}
#define CP16(dst, src) \
    asm volatile("cp.async.cg.shared.global [%0], [%1], 16;" :: "r"(dst), "l"(src) : "memory")
#define CP_COMMIT() asm volatile("cp.async.commit_group;" ::: "memory")
#define CP_WAIT1()  asm volatile("cp.async.wait_group 1;" ::: "memory")

__device__ __forceinline__ void ldsm_x4(uint32_t a[4], uint32_t addr) {
    asm volatile("ldmatrix.sync.aligned.m8n8.x4.shared.b16 {%0,%1,%2,%3}, [%4];"
        : "=r"(a[0]), "=r"(a[1]), "=r"(a[2]), "=r"(a[3]) : "r"(addr));
}
__device__ __forceinline__ void ldsm_x2(uint32_t a[2], uint32_t addr) {
    asm volatile("ldmatrix.sync.aligned.m8n8.x2.shared.b16 {%0,%1}, [%2];"
        : "=r"(a[0]), "=r"(a[1]) : "r"(addr));
}
__device__ __forceinline__ uint32_t cvt_tf32(uint32_t x) {
    uint32_t r;
    asm("cvt.rna.tf32.f32 %0, %1;" : "=r"(r) : "f"(__uint_as_float(x)));
    return r;
}
__device__ __forceinline__ void mma_tf32(float c[4], const uint32_t a[4], const uint32_t b[2]) {
    asm volatile(
        "mma.sync.aligned.m16n8k8.row.col.f32.tf32.tf32.f32 "
        "{%0,%1,%2,%3}, {%4,%5,%6,%7}, {%8,%9}, {%0,%1,%2,%3};"
        : "+f"(c[0]), "+f"(c[1]), "+f"(c[2]), "+f"(c[3])
        : "r"(a[0]), "r"(a[1]), "r"(a[2]), "r"(a[3]), "r"(b[0]), "r"(b[1]));
}

// packed f32x2 ops (base sm_100 ISA feature, valid on compute_103)
#define FMA2(d, a, b) \
    asm("fma.rn.f32x2 %0, %1, %2, %0;" : "+l"(d) : "l"(a), "l"(b))
#define MUL2(d, a, b) \
    asm("mul.rn.f32x2 %0, %1, %2;" : "=l"(d) : "l"(a), "l"(b))
#define PACK2(d, lo, hi) \
    asm("mov.b64 %0, {%1, %2};" : "=l"(d) : "f"(lo), "f"(hi))
#define UNPACK2(lo, hi, s) \
    asm("mov.b64 {%0, %1}, %2;" : "=f"(lo), "=f"(hi) : "l"(s))

// ---------------------------------------------------------------------------
// TF32 mma.sync GEMM: C[M,N] = A[M,K] @ B[N,K]^T + bias[N]   (unchanged R3)
// ---------------------------------------------------------------------------
#define BKC 32
#define STAGE_BYTES 32768
#define GEMM_SMEM (3 * STAGE_BYTES)

__global__ void __launch_bounds__(256) gemm_tf32(
    const float* __restrict__ A, const float* __restrict__ B,
    const float* __restrict__ bias, float* __restrict__ C,
    int M, int N, int K)
{
    extern __shared__ char smem[];
    const uint32_t sb = smem_u32(smem);
    const int tid  = threadIdx.x;
    const int lane = tid & 31;
    const int wid  = tid >> 5;
    const int row0 = blockIdx.y * 128;
    const int col0 = blockIdx.x * 128;
    const int wm = (wid >> 2) * 64;
    const int wn = (wid & 3) * 32;

    const int r = tid >> 3;
    const int c = tid & 7;
    const float* aSrc = A + (size_t)(row0 + r) * K + c * 4;
    const float* bSrc = B + (size_t)(col0 + r) * K + c * 4;
    uint32_t dOff[4];
    #pragma unroll
    for (int l = 0; l < 4; l++) {
        int row = r + 32 * l;
        dOff[l] = (uint32_t)(row * 128 + ((c * 16) ^ ((row & 7) << 4)));
    }

    const int nk = K / BKC;

    uint32_t aRow[4], bRow[4];
    #pragma unroll
    for (int mi = 0; mi < 4; mi++) aRow[mi] = (uint32_t)((wm + mi * 16 + (lane & 15)) * 128);
    #pragma unroll
    for (int ni = 0; ni < 4; ni++) bRow[ni] = (uint32_t)((wn + ni * 8 + (lane & 7)) * 128);
    const uint32_t xorv = (uint32_t)((lane & 7) << 4);
    const uint32_t aseg = (uint32_t)((lane >> 4) * 16);
    const uint32_t bseg = (uint32_t)(((lane >> 3) & 1) * 16);

    float acc[16][4];
    #pragma unroll
    for (int t = 0; t < 16; t++)
        #pragma unroll
        for (int j = 0; j < 4; j++) acc[t][j] = 0.f;

    #pragma unroll
    for (int p = 0; p < 2; p++) {
        uint32_t base = sb + p * STAGE_BYTES;
        size_t koff = (size_t)p * BKC;
        #pragma unroll
        for (int l = 0; l < 4; l++) CP16(base + dOff[l],         aSrc + (size_t)l * 32 * K + koff);
        #pragma unroll
        for (int l = 0; l < 4; l++) CP16(base + 16384 + dOff[l], bSrc + (size_t)l * 32 * K + koff);
        CP_COMMIT();
    }

    int sCur = 0, sNext = 2;
    for (int i = 0; i < nk; i++) {
        CP_WAIT1();
        __syncthreads();

        if (i + 2 < nk) {
            uint32_t base = sb + sNext * STAGE_BYTES;
            size_t koff = (size_t)(i + 2) * BKC;
            #pragma unroll
            for (int l = 0; l < 4; l++) CP16(base + dOff[l],         aSrc + (size_t)l * 32 * K + koff);
            #pragma unroll
            for (int l = 0; l < 4; l++) CP16(base + 16384 + dOff[l], bSrc + (size_t)l * 32 * K + koff);
        }
        CP_COMMIT();

        const uint32_t aBase = sb + sCur * STAGE_BYTES;
        const uint32_t bBase = aBase + 16384;

        #pragma unroll
        for (int ks = 0; ks < 4; ks++) {
            const uint32_t kb = (uint32_t)(ks * 32);
            uint32_t af[4][4], bf[4][2];
            #pragma unroll
            for (int mi = 0; mi < 4; mi++)
                ldsm_x4(af[mi], aBase + aRow[mi] + ((kb + aseg) ^ xorv));
            #pragma unroll
            for (int ni = 0; ni < 4; ni++)
                ldsm_x2(bf[ni], bBase + bRow[ni] + ((kb + bseg) ^ xorv));
            #pragma unroll
            for (int mi = 0; mi < 4; mi++)
                #pragma unroll
                for (int j = 0; j < 4; j++) af[mi][j] = cvt_tf32(af[mi][j]);
            #pragma unroll
            for (int ni = 0; ni < 4; ni++) {
                bf[ni][0] = cvt_tf32(bf[ni][0]);
                bf[ni][1] = cvt_tf32(bf[ni][1]);
            }
            #pragma unroll
            for (int mi = 0; mi < 4; mi++)
                #pragma unroll
                for (int ni = 0; ni < 4; ni++)
                    mma_tf32(acc[mi * 4 + ni], af[mi], bf[ni]);
        }

        sCur = (sCur + 1) % 3;
        sNext = (sNext + 1) % 3;
    }

    const int gq = lane >> 2;
    const int qc = lane & 3;
    #pragma unroll
    for (int mi = 0; mi < 4; mi++) {
        #pragma unroll
        for (int ni = 0; ni < 4; ni++) {
            const float* ac = acc[mi * 4 + ni];
            int colb = col0 + wn + ni * 8 + qc * 2;
            float b0 = __ldg(&bias[colb]);
            float b1 = __ldg(&bias[colb + 1]);
            size_t base0 = (size_t)(row0 + wm + mi * 16 + gq) * N + colb;
            C[base0]         = ac[0] + b0;
            C[base0 + 1]     = ac[1] + b1;
            C[base0 + 8 * (size_t)N]     = ac[2] + b0;
            C[base0 + 8 * (size_t)N + 1] = ac[3] + b1;
        }
    }
}

// ---------------------------------------------------------------------------
// RoPE + transpose (unchanged)
// ---------------------------------------------------------------------------
__global__ void __launch_bounds__(256) rope_transpose(
    const float* __restrict__ qkv, const float* __restrict__ rope,
    float* __restrict__ q, float* __restrict__ k, float* __restrict__ v)
{
    int idx = blockIdx.x * 256 + threadIdx.x;
    int d = idx & 63;
    int h = (idx >> 6) & 31;
    int t = (idx >> 11) & 1023;
    int b = idx >> 21;

    const float* row = qkv + (size_t)(b * SEQ + t) * QKVN;
    int col = h * HDIM + d;

    float qv, kv;
    if (d < 32) {
        int j = d & 15;
        float cs = rope[(t * 16 + j) * 2 + 0];
        float sn = rope[(t * 16 + j) * 2 + 1];
        if (d < 16) {
            qv = row[col]        * cs - row[col + 16]        * sn;
            kv = row[CDIM + col] * cs - row[CDIM + col + 16] * sn;
        } else {
            qv = row[col]        * cs + row[col - 16]        * sn;
            kv = row[CDIM + col] * cs + row[CDIM + col - 16] * sn;
        }
    } else {
        qv = row[col];
        kv = row[CDIM + col];
    }
    float vv = row[2 * CDIM + col];

    size_t o = ((size_t)(b * NHEAD + h) * SEQ + t) * HDIM + d;
    q[o] = qv; k[o] = kv; v[o] = vv;
}

// ---------------------------------------------------------------------------
// Causal flash attention, fp32 with packed f32x2 FMAs.
// Row stride 70 floats (280B): 8B-aligned rows, 16-row LDS.64 conflict-free.
// ---------------------------------------------------------------------------
#define ASTRIDE 70
#define ATTN_SMEM (4 * 64 * ASTRIDE * 4)   // 71680

__global__ void __launch_bounds__(256) attn_kernel(
    const float* __restrict__ Q, const float* __restrict__ K,
    const float* __restrict__ V, float* __restrict__ ctx)
{
    extern __shared__ float sm[];
    float* qs = sm;
    float* ks = sm + 64 * ASTRIDE;
    float* vs = sm + 2 * 64 * ASTRIDE;
    float* ps = sm + 3 * 64 * ASTRIDE;

    const int bh = blockIdx.y;
    const int b  = bh >> 5;
    const int h  = bh & 31;
    const int qt = blockIdx.x;
    const int q0 = qt * 64;
    const int tid = threadIdx.x;
    const int rg = tid >> 4;
    const int cg = tid & 15;
    const int lane = tid & 31;

    // stage Q (float2 stores; warp w writes rows w+8l, lanes across 32 col-pairs)
    const float* Qb = Q + ((size_t)bh * SEQ + q0) * HDIM;
    const int wrp = tid >> 5;
    {
        const float2* Qb2 = (const float2*)Qb;
        #pragma unroll
        for (int l = 0; l < 8; l++) {
            int row = wrp + 8 * l;
            float2 t2 = Qb2[row * 32 + lane];
            *(float2*)&qs[row * ASTRIDE + lane * 2] = t2;
        }
    }

    ull acc2[4][2];
    float mrow[4], lrow[4];
    #pragma unroll
    for (int i = 0; i < 4; i++) {
        mrow[i] = -1e30f; lrow[i] = 0.f;
        acc2[i][0] = 0ull; acc2[i][1] = 0ull;
    }
    const float scale = 0.125f;

    const int prow = rg * 4;         // this thread's P/Q row base
    const int pcol = cg * 4;         // this thread's col base

    for (int kt = 0; kt <= qt; kt++) {
        const int k0 = kt * 64;
        const float2* Kb2 = (const float2*)(K + ((size_t)bh * SEQ + k0) * HDIM);
        const float2* Vb2 = (const float2*)(V + ((size_t)bh * SEQ + k0) * HDIM);

        __syncthreads();
        #pragma unroll
        for (int l = 0; l < 8; l++) {
            int row = wrp + 8 * l;
            float2 kk = Kb2[row * 32 + lane];
            *(float2*)&ks[row * ASTRIDE + lane * 2] = kk;
            float2 vv = Vb2[row * 32 + lane];
            *(float2*)&vs[row * ASTRIDE + lane * 2] = vv;
        }
        __syncthreads();

        // S = Q K^T, packed over d pairs
        ull s2[4][4];
        #pragma unroll
        for (int i = 0; i < 4; i++)
            #pragma unroll
            for (int j = 0; j < 4; j++) s2[i][j] = 0ull;

        #pragma unroll 4
        for (int d2 = 0; d2 < 32; d2++) {
            ull q2[4], k2[4];
            #pragma unroll
            for (int i = 0; i < 4; i++) q2[i] = *(const ull*)&qs[(prow + i) * ASTRIDE + d2 * 2];
            #pragma unroll
            for (int j = 0; j < 4; j++) k2[j] = *(const ull*)&ks[(pcol + j) * ASTRIDE + d2 * 2];
            #pragma unroll
            for (int i = 0; i < 4; i++)
                #pragma unroll
                for (int j = 0; j < 4; j++)
                    FMA2(s2[i][j], q2[i], k2[j]);
        }

        float s[4][4];
        const bool diag = (kt == qt);
        #pragma unroll
        for (int i = 0; i < 4; i++)
            #pragma unroll
            for (int j = 0; j < 4; j++) {
                float lo, hi;
                UNPACK2(lo, hi, s2[i][j]);
                float val = (lo + hi) * scale;
                if (diag && (k0 + pcol + j > q0 + prow + i)) val = -1e30f;
                s[i][j] = val;
            }

        // online softmax update
        #pragma unroll
        for (int i = 0; i < 4; i++) {
            float mx = s[i][0];
            #pragma unroll
            for (int j = 1; j < 4; j++) mx = fmaxf(mx, s[i][j]);
            #pragma unroll
            for (int off = 8; off; off >>= 1)
                mx = fmaxf(mx, __shfl_xor_sync(0xffffffffu, mx, off));

            float mn   = fmaxf(mrow[i], mx);
            float corr = __expf(mrow[i] - mn);
            float rs   = 0.f;
            float p[4];
            #pragma unroll
            for (int j = 0; j < 4; j++) { p[j] = __expf(s[i][j] - mn); rs += p[j]; }
            #pragma unroll
            for (int off = 8; off; off >>= 1)
                rs += __shfl_xor_sync(0xffffffffu, rs, off);

            lrow[i] = lrow[i] * corr + rs;
            mrow[i] = mn;
            ull corr2; PACK2(corr2, corr, corr);
            MUL2(acc2[i][0], acc2[i][0], corr2);
            MUL2(acc2[i][1], acc2[i][1], corr2);
            #pragma unroll
            for (int j = 0; j < 4; j++) ps[(prow + i) * ASTRIDE + pcol + j] = p[j];
        }
        __syncthreads();

        // acc += P @ V   (packed over output-col pairs)
        #pragma unroll 4
        for (int cc = 0; cc < 64; cc++) {
            ull v2[2];
            v2[0] = *(const ull*)&vs[cc * ASTRIDE + pcol];
            v2[1] = *(const ull*)&vs[cc * ASTRIDE + pcol + 2];
            #pragma unroll
            for (int i = 0; i < 4; i++) {
                float pv = ps[(prow + i) * ASTRIDE + cc];
                ull p2; PACK2(p2, pv, pv);
                FMA2(acc2[i][0], p2, v2[0]);
                FMA2(acc2[i][1], p2, v2[1]);
            }
        }
    }

    // write ctx in [B, T, C] layout
    #pragma unroll
    for (int i = 0; i < 4; i++) {
        int t = q0 + prow + i;
        float inv = 1.f / lrow[i];
        size_t base = ((size_t)b * SEQ + t) * CDIM + h * HDIM + pcol;
        float a0, a1, a2, a3;
        UNPACK2(a0, a1, acc2[i][0]);
        UNPACK2(a2, a3, acc2[i][1]);
        ctx[base]     = a0 * inv;
        ctx[base + 1] = a1 * inv;
        ctx[base + 2] = a2 * inv;
        ctx[base + 3] = a3 * inv;
    }
}

// ---------------------------------------------------------------------------
extern "C" void kernel_launch(void* const* d_in, const int* in_sizes, int n_in,
                              void* d_out, int out_size)
{
    const float* x      = (const float*)d_in[0];
    const float* rope   = (const float*)d_in[3];
    const float* Wqkv_w = (const float*)d_in[4];
    const float* Wqkv_b = (const float*)d_in[5];
    const float* out_w  = (const float*)d_in[6];
    const float* out_b  = (const float*)d_in[7];
    float* out = (float*)d_out;

    float *qkv, *q, *k, *v;
    cudaGetSymbolAddress((void**)&qkv, g_qkv);
    cudaGetSymbolAddress((void**)&q,   g_q);
    cudaGetSymbolAddress((void**)&k,   g_k);
    cudaGetSymbolAddress((void**)&v,   g_v);
    float* ctx = qkv;

    cudaFuncSetAttribute(gemm_tf32, cudaFuncAttributeMaxDynamicSharedMemorySize, GEMM_SMEM);
    cudaFuncSetAttribute(attn_kernel, cudaFuncAttributeMaxDynamicSharedMemorySize, ATTN_SMEM);

    // 1) QKV projection (tf32 tensor cores)
    gemm_tf32<<<dim3(QKVN / 128, MROWS / 128), 256, GEMM_SMEM>>>(
        x, Wqkv_w, Wqkv_b, qkv, MROWS, QKVN, CDIM);

    // 2) RoPE + transpose
    rope_transpose<<<(BATCH * SEQ * NHEAD * HDIM) / 256, 256>>>(qkv, rope, q, k, v);

    // 3) causal attention (f32x2 packed math)
    attn_kernel<<<dim3(SEQ / 64, BATCH * NHEAD), 256, ATTN_SMEM>>>(q, k, v, ctx);

    // 4) output projection (tf32 tensor cores)
    gemm_tf32<<<dim3(CDIM / 128, MROWS / 128), 256, GEMM_SMEM>>>(
        ctx, out_w, out_b, out, MROWS, CDIM, CDIM);
}

// round 5
// speedup vs baseline: 1.1337x; 1.1337x over previous
#include <cuda_runtime.h>
#include <cuda_bf16.h>
#include <cstdint>

// Problem constants
#define BATCH 4
#define SEQ   1024
#define CDIM  2048
#define NHEAD 32
#define HDIM  64
#define QKVN  (3*CDIM)          // 6144
#define MROWS (BATCH*SEQ)       // 4096

// Scratch (device globals: allocation-free rule)
__device__ float g_qkv[(size_t)MROWS * QKVN];
__device__ float g_q[(size_t)BATCH*NHEAD*SEQ*HDIM];
__device__ float g_k[(size_t)BATCH*NHEAD*SEQ*HDIM];
__device__ float g_v[(size_t)BATCH*NHEAD*SEQ*HDIM];
// tf32-pre-rounded operand copies
__device__ float g_xc[(size_t)MROWS * CDIM];
__device__ float g_w1[(size_t)QKVN * CDIM];
__device__ float g_w2[(size_t)CDIM * CDIM];

// ---------------------------------------------------------------------------
// helpers
// ---------------------------------------------------------------------------
__device__ __forceinline__ uint32_t smem_u32(const void* p) {
    uint32_t a;
    asm("{ .reg .u64 t; cvta.to.shared.u64 t, %1; cvt.u32.u64 %0, t; }" : "=r"(a) : "l"(p));
    return a;
}
#define CP16(dst, src) \
    asm volatile("cp.async.cg.shared.global [%0], [%1], 16;" :: "r"(dst), "l"(src) : "memory")
#define CP_COMMIT() asm volatile("cp.async.commit_group;" ::: "memory")
#define CP_WAIT1()  asm volatile("cp.async.wait_group 1;" ::: "memory")

__device__ __forceinline__ void ldsm_x4(uint32_t a[4], uint32_t addr) {
    asm volatile("ldmatrix.sync.aligned.m8n8.x4.shared.b16 {%0,%1,%2,%3}, [%4];"
        : "=r"(a[0]), "=r"(a[1]), "=r"(a[2]), "=r"(a[3]) : "r"(addr));
}
__device__ __forceinline__ void ldsm_x2(uint32_t a[2], uint32_t addr) {
    asm volatile("ldmatrix.sync.aligned.m8n8.x2.shared.b16 {%0,%1}, [%2];"
        : "=r"(a[0]), "=r"(a[1]) : "r"(addr));
}
__device__ __forceinline__ float cvt_tf32_f(float x) {
    uint32_t r;
    asm("cvt.rna.tf32.f32 %0, %1;" : "=r"(r) : "f"(x));
    return __uint_as_float(r);
}
__device__ __forceinline__ void mma_tf32(float c[4], const uint32_t a[4], const uint32_t b[2]) {
    asm volatile(
        "mma.sync.aligned.m16n8k8.row.col.f32.tf32.tf32.f32 "
        "{%0,%1,%2,%3}, {%4,%5,%6,%7}, {%8,%9}, {%0,%1,%2,%3};"
        : "+f"(c[0]), "+f"(c[1]), "+f"(c[2]), "+f"(c[3])
        : "r"(a[0]), "r"(a[1]), "r"(a[2]), "r"(a[3]), "r"(b[0]), "r"(b[1]));
}

// ---------------------------------------------------------------------------
// tf32 pre-round pass: out[i] = rna_tf32(in[i])  (idempotent)
// ---------------------------------------------------------------------------
__global__ void __launch_bounds__(256) cvt_tf32_copy(
    const float* __restrict__ in, float* __restrict__ out, int n4)
{
    int i = blockIdx.x * 256 + threadIdx.x;
    if (i < n4) {
        float4 v = reinterpret_cast<const float4*>(in)[i];
        v.x = cvt_tf32_f(v.x); v.y = cvt_tf32_f(v.y);
        v.z = cvt_tf32_f(v.z); v.w = cvt_tf32_f(v.w);
        reinterpret_cast<float4*>(out)[i] = v;
    }
}

// ---------------------------------------------------------------------------
// TF32 mma.sync GEMM: C[M,N] = A[M,K] @ B[N,K]^T + bias[N]
// Operands must be pre-rounded to tf32 bit patterns. No cvt in mainloop.
// ---------------------------------------------------------------------------
#define BKC 32
#define STAGE_BYTES 32768
#define GEMM_SMEM (3 * STAGE_BYTES)

__global__ void __launch_bounds__(256) gemm_tf32(
    const float* __restrict__ A, const float* __restrict__ B,
    const float* __restrict__ bias, float* __restrict__ C,
    int M, int N, int K)
{
    extern __shared__ char smem[];
    const uint32_t sb = smem_u32(smem);
    const int tid  = threadIdx.x;
    const int lane = tid & 31;
    const int wid  = tid >> 5;
    const int row0 = blockIdx.y * 128;
    const int col0 = blockIdx.x * 128;
    const int wm = (wid >> 2) * 64;
    const int wn = (wid & 3) * 32;

    const int r = tid >> 3;
    const int c = tid & 7;
    const float* aSrc = A + (size_t)(row0 + r) * K + c * 4;
    const float* bSrc = B + (size_t)(col0 + r) * K + c * 4;
    uint32_t dOff[4];
    #pragma unroll
    for (int l = 0; l < 4; l++) {
        int row = r + 32 * l;
        dOff[l] = (uint32_t)(row * 128 + ((c * 16) ^ ((row & 7) << 4)));
    }

    const int nk = K / BKC;

    uint32_t aRow[4], bRow[4];
    #pragma unroll
    for (int mi = 0; mi < 4; mi++) aRow[mi] = (uint32_t)((wm + mi * 16 + (lane & 15)) * 128);
    #pragma unroll
    for (int ni = 0; ni < 4; ni++) bRow[ni] = (uint32_t)((wn + ni * 8 + (lane & 7)) * 128);
    const uint32_t xorv = (uint32_t)((lane & 7) << 4);
    const uint32_t aseg = (uint32_t)((lane >> 4) * 16);
    const uint32_t bseg = (uint32_t)(((lane >> 3) & 1) * 16);

    float acc[16][4];
    #pragma unroll
    for (int t = 0; t < 16; t++)
        #pragma unroll
        for (int j = 0; j < 4; j++) acc[t][j] = 0.f;

    #pragma unroll
    for (int p = 0; p < 2; p++) {
        uint32_t base = sb + p * STAGE_BYTES;
        size_t koff = (size_t)p * BKC;
        #pragma unroll
        for (int l = 0; l < 4; l++) CP16(base + dOff[l],         aSrc + (size_t)l * 32 * K + koff);
        #pragma unroll
        for (int l = 0; l < 4; l++) CP16(base + 16384 + dOff[l], bSrc + (size_t)l * 32 * K + koff);
        CP_COMMIT();
    }

    int sCur = 0, sNext = 2;
    for (int i = 0; i < nk; i++) {
        CP_WAIT1();
        __syncthreads();

        if (i + 2 < nk) {
            uint32_t base = sb + sNext * STAGE_BYTES;
            size_t koff = (size_t)(i + 2) * BKC;
            #pragma unroll
            for (int l = 0; l < 4; l++) CP16(base + dOff[l],         aSrc + (size_t)l * 32 * K + koff);
            #pragma unroll
            for (int l = 0; l < 4; l++) CP16(base + 16384 + dOff[l], bSrc + (size_t)l * 32 * K + koff);
        }
        CP_COMMIT();

        const uint32_t aBase = sb + sCur * STAGE_BYTES;
        const uint32_t bBase = aBase + 16384;

        #pragma unroll
        for (int ks = 0; ks < 4; ks++) {
            const uint32_t kb = (uint32_t)(ks * 32);
            uint32_t af[4][4], bf[4][2];
            #pragma unroll
            for (int mi = 0; mi < 4; mi++)
                ldsm_x4(af[mi], aBase + aRow[mi] + ((kb + aseg) ^ xorv));
            #pragma unroll
            for (int ni = 0; ni < 4; ni++)
                ldsm_x2(bf[ni], bBase + bRow[ni] + ((kb + bseg) ^ xorv));
            #pragma unroll
            for (int mi = 0; mi < 4; mi++)
                #pragma unroll
                for (int ni = 0; ni < 4; ni++)
                    mma_tf32(acc[mi * 4 + ni], af[mi], bf[ni]);
        }

        sCur = (sCur + 1) % 3;
        sNext = (sNext + 1) % 3;
    }

    const int gq = lane >> 2;
    const int qc = lane & 3;
    #pragma unroll
    for (int mi = 0; mi < 4; mi++) {
        #pragma unroll
        for (int ni = 0; ni < 4; ni++) {
            const float* ac = acc[mi * 4 + ni];
            int colb = col0 + wn + ni * 8 + qc * 2;
            float b0 = __ldg(&bias[colb]);
            float b1 = __ldg(&bias[colb + 1]);
            size_t base0 = (size_t)(row0 + wm + mi * 16 + gq) * N + colb;
            C[base0]         = ac[0] + b0;
            C[base0 + 1]     = ac[1] + b1;
            C[base0 + 8 * (size_t)N]     = ac[2] + b0;
            C[base0 + 8 * (size_t)N + 1] = ac[3] + b1;
        }
    }
}

// ---------------------------------------------------------------------------
// RoPE + transpose (unchanged)
// ---------------------------------------------------------------------------
__global__ void __launch_bounds__(256) rope_transpose(
    const float* __restrict__ qkv, const float* __restrict__ rope,
    float* __restrict__ q, float* __restrict__ k, float* __restrict__ v)
{
    int idx = blockIdx.x * 256 + threadIdx.x;
    int d = idx & 63;
    int h = (idx >> 6) & 31;
    int t = (idx >> 11) & 1023;
    int b = idx >> 21;

    const float* row = qkv + (size_t)(b * SEQ + t) * QKVN;
    int col = h * HDIM + d;

    float qv, kv;
    if (d < 32) {
        int j = d & 15;
        float cs = rope[(t * 16 + j) * 2 + 0];
        float sn = rope[(t * 16 + j) * 2 + 1];
        if (d < 16) {
            qv = row[col]        * cs - row[col + 16]        * sn;
            kv = row[CDIM + col] * cs - row[CDIM + col + 16] * sn;
        } else {
            qv = row[col]        * cs + row[col - 16]        * sn;
            kv = row[CDIM + col] * cs + row[CDIM + col - 16] * sn;
        }
    } else {
        qv = row[col];
        kv = row[CDIM + col];
    }
    float vv = row[2 * CDIM + col];

    size_t o = ((size_t)(b * NHEAD + h) * SEQ + t) * HDIM + d;
    q[o] = qv; k[o] = kv; v[o] = vv;
}

// ---------------------------------------------------------------------------
// Causal flash attention, fp32 scalar (R3 version; ctx stores tf32-rounded).
// ---------------------------------------------------------------------------
#define ATTN_SMEM (4 * 64 * 65 * 4)   // 66560

__global__ void __launch_bounds__(256) attn_kernel(
    const float* __restrict__ Q, const float* __restrict__ K,
    const float* __restrict__ V, float* __restrict__ ctx)
{
    extern __shared__ float sm[];
    float (*qs)[65] = (float(*)[65])(sm);
    float (*ks)[65] = (float(*)[65])(sm + 64 * 65);
    float (*vs)[65] = (float(*)[65])(sm + 2 * 64 * 65);
    float (*ps)[65] = (float(*)[65])(sm + 3 * 64 * 65);

    const int bh = blockIdx.y;
    const int b  = bh >> 5;
    const int h  = bh & 31;
    const int qt = blockIdx.x;
    const int q0 = qt * 64;
    const int tid = threadIdx.x;
    const int rg = tid >> 4;
    const int cg = tid & 15;

    const float* Qb = Q + ((size_t)bh * SEQ + q0) * HDIM;
    #pragma unroll
    for (int l2 = 0; l2 < 4; l2++) {
        int id = tid + l2 * 256;
        int r  = id >> 4;
        int c4 = (id & 15) << 2;
        float4 v4 = *reinterpret_cast<const float4*>(Qb + r * HDIM + c4);
        qs[r][c4] = v4.x; qs[r][c4 + 1] = v4.y; qs[r][c4 + 2] = v4.z; qs[r][c4 + 3] = v4.w;
    }

    float acc[4][4];
    float mrow[4], lrow[4];
    #pragma unroll
    for (int i = 0; i < 4; i++) {
        mrow[i] = -1e30f; lrow[i] = 0.f;
        #pragma unroll
        for (int j = 0; j < 4; j++) acc[i][j] = 0.f;
    }
    const float scale = 0.125f;

    for (int kt = 0; kt <= qt; kt++) {
        const int k0 = kt * 64;
        const float* Kb = K + ((size_t)bh * SEQ + k0) * HDIM;
        const float* Vb = V + ((size_t)bh * SEQ + k0) * HDIM;

        __syncthreads();
        #pragma unroll
        for (int l2 = 0; l2 < 4; l2++) {
            int id = tid + l2 * 256;
            int r  = id >> 4;
            int c4 = (id & 15) << 2;
            float4 k4 = *reinterpret_cast<const float4*>(Kb + r * HDIM + c4);
            ks[r][c4] = k4.x; ks[r][c4 + 1] = k4.y; ks[r][c4 + 2] = k4.z; ks[r][c4 + 3] = k4.w;
            float4 v4 = *reinterpret_cast<const float4*>(Vb + r * HDIM + c4);
            vs[r][c4] = v4.x; vs[r][c4 + 1] = v4.y; vs[r][c4 + 2] = v4.z; vs[r][c4 + 3] = v4.w;
        }
        __syncthreads();

        float s[4][4];
        #pragma unroll
        for (int i = 0; i < 4; i++)
            #pragma unroll
            for (int j = 0; j < 4; j++) s[i][j] = 0.f;

        #pragma unroll 8
        for (int d = 0; d < 64; d++) {
            float qv[4], kv[4];
            #pragma unroll
            for (int i = 0; i < 4; i++) qv[i] = qs[rg * 4 + i][d];
            #pragma unroll
            for (int j = 0; j < 4; j++) kv[j] = ks[cg * 4 + j][d];
            #pragma unroll
            for (int i = 0; i < 4; i++)
                #pragma unroll
                for (int j = 0; j < 4; j++)
                    s[i][j] += qv[i] * kv[j];
        }

        const bool diag = (kt == qt);
        #pragma unroll
        for (int i = 0; i < 4; i++)
            #pragma unroll
            for (int j = 0; j < 4; j++) {
                float val = s[i][j] * scale;
                if (diag && (k0 + cg * 4 + j > q0 + rg * 4 + i)) val = -1e30f;
                s[i][j] = val;
            }

        #pragma unroll
        for (int i = 0; i < 4; i++) {
            float mx = s[i][0];
            #pragma unroll
            for (int j = 1; j < 4; j++) mx = fmaxf(mx, s[i][j]);
            #pragma unroll
            for (int off = 8; off; off >>= 1)
                mx = fmaxf(mx, __shfl_xor_sync(0xffffffffu, mx, off));

            float mn   = fmaxf(mrow[i], mx);
            float corr = __expf(mrow[i] - mn);
            float rs   = 0.f;
            float p[4];
            #pragma unroll
            for (int j = 0; j < 4; j++) { p[j] = __expf(s[i][j] - mn); rs += p[j]; }
            #pragma unroll
            for (int off = 8; off; off >>= 1)
                rs += __shfl_xor_sync(0xffffffffu, rs, off);

            lrow[i] = lrow[i] * corr + rs;
            mrow[i] = mn;
            #pragma unroll
            for (int j = 0; j < 4; j++) acc[i][j] *= corr;
            #pragma unroll
            for (int j = 0; j < 4; j++) ps[rg * 4 + i][cg * 4 + j] = p[j];
        }
        __syncthreads();

        #pragma unroll 8
        for (int cc = 0; cc < 64; cc++) {
            float pv[4], vv[4];
            #pragma unroll
            for (int i = 0; i < 4; i++) pv[i] = ps[rg * 4 + i][cc];
            #pragma unroll
            for (int j = 0; j < 4; j++) vv[j] = vs[cc][cg * 4 + j];
            #pragma unroll
            for (int i = 0; i < 4; i++)
                #pragma unroll
                for (int j = 0; j < 4; j++)
                    acc[i][j] += pv[i] * vv[j];
        }
    }

    // ctx is consumed only as GEMM-A: store tf32-pre-rounded values
    #pragma unroll
    for (int i = 0; i < 4; i++) {
        int t = q0 + rg * 4 + i;
        float inv = 1.f / lrow[i];
        size_t base = ((size_t)b * SEQ + t) * CDIM + h * HDIM + cg * 4;
        #pragma unroll
        for (int j = 0; j < 4; j++)
            ctx[base + j] = cvt_tf32_f(acc[i][j] * inv);
    }
}

// ---------------------------------------------------------------------------
extern "C" void kernel_launch(void* const* d_in, const int* in_sizes, int n_in,
                              void* d_out, int out_size)
{
    const float* x      = (const float*)d_in[0];
    const float* rope   = (const float*)d_in[3];
    const float* Wqkv_w = (const float*)d_in[4];
    const float* Wqkv_b = (const float*)d_in[5];
    const float* out_w  = (const float*)d_in[6];
    const float* out_b  = (const float*)d_in[7];
    float* out = (float*)d_out;

    float *qkv, *q, *k, *v, *xc, *w1, *w2;
    cudaGetSymbolAddress((void**)&qkv, g_qkv);
    cudaGetSymbolAddress((void**)&q,   g_q);
    cudaGetSymbolAddress((void**)&k,   g_k);
    cudaGetSymbolAddress((void**)&v,   g_v);
    cudaGetSymbolAddress((void**)&xc,  g_xc);
    cudaGetSymbolAddress((void**)&w1,  g_w1);
    cudaGetSymbolAddress((void**)&w2,  g_w2);
    float* ctx = qkv;

    cudaFuncSetAttribute(gemm_tf32, cudaFuncAttributeMaxDynamicSharedMemorySize, GEMM_SMEM);
    cudaFuncSetAttribute(attn_kernel, cudaFuncAttributeMaxDynamicSharedMemorySize, ATTN_SMEM);

    // 0) pre-round GEMM operands to tf32 bit patterns
    cvt_tf32_copy<<<(MROWS * CDIM / 4 + 255) / 256, 256>>>(x,      xc, MROWS * CDIM / 4);
    cvt_tf32_copy<<<(QKVN  * CDIM / 4 + 255) / 256, 256>>>(Wqkv_w, w1, QKVN  * CDIM / 4);
    cvt_tf32_copy<<<(CDIM  * CDIM / 4 + 255) / 256, 256>>>(out_w,  w2, CDIM  * CDIM / 4);

    // 1) QKV projection (tf32 tensor cores, no mainloop cvt)
    gemm_tf32<<<dim3(QKVN / 128, MROWS / 128), 256, GEMM_SMEM>>>(
        xc, w1, Wqkv_b, qkv, MROWS, QKVN, CDIM);

    // 2) RoPE + transpose
    rope_transpose<<<(BATCH * SEQ * NHEAD * HDIM) / 256, 256>>>(qkv, rope, q, k, v);

    // 3) causal attention (fp32 scalar, ctx pre-rounded on store)
    attn_kernel<<<dim3(SEQ / 64, BATCH * NHEAD), 256, ATTN_SMEM>>>(q, k, v, ctx);

    // 4) output projection (tf32 tensor cores)
    gemm_tf32<<<dim3(CDIM / 128, MROWS / 128), 256, GEMM_SMEM>>>(
        ctx, w2, out_b, out, MROWS, CDIM, CDIM);
}

// round 6
// speedup vs baseline: 1.1482x; 1.0128x over previous
#include <cuda_runtime.h>
#include <cuda_bf16.h>
#include <cstdint>

// Problem constants
#define BATCH 4
#define SEQ   1024
#define CDIM  2048
#define NHEAD 32
#define HDIM  64
#define QKVN  (3*CDIM)          // 6144
#define MROWS (BATCH*SEQ)       // 4096

// Scratch (device globals: allocation-free rule)
__device__ float g_qkv[(size_t)MROWS * QKVN];
__device__ float g_q[(size_t)BATCH*NHEAD*SEQ*HDIM];
__device__ float g_k[(size_t)BATCH*NHEAD*SEQ*HDIM];
__device__ float g_v[(size_t)BATCH*NHEAD*SEQ*HDIM];
// tf32-pre-rounded operand copies
__device__ float g_xc[(size_t)MROWS * CDIM];
__device__ float g_w1[(size_t)QKVN * CDIM];
__device__ float g_w2[(size_t)CDIM * CDIM];

// ---------------------------------------------------------------------------
// helpers
// ---------------------------------------------------------------------------
__device__ __forceinline__ uint32_t smem_u32(const void* p) {
    uint32_t a;
    asm("{ .reg .u64 t; cvta.to.shared.u64 t, %1; cvt.u32.u64 %0, t; }" : "=r"(a) : "l"(p));
    return a;
}
#define CP16(dst, src) \
    asm volatile("cp.async.cg.shared.global [%0], [%1], 16;" :: "r"(dst), "l"(src) : "memory")
#define CP_COMMIT() asm volatile("cp.async.commit_group;" ::: "memory")
#define CP_WAIT1()  asm volatile("cp.async.wait_group 1;" ::: "memory")

__device__ __forceinline__ void ldsm_x4(uint32_t a[4], uint32_t addr) {
    asm volatile("ldmatrix.sync.aligned.m8n8.x4.shared.b16 {%0,%1,%2,%3}, [%4];"
        : "=r"(a[0]), "=r"(a[1]), "=r"(a[2]), "=r"(a[3]) : "r"(addr));
}
__device__ __forceinline__ void ldsm_x2(uint32_t a[2], uint32_t addr) {
    asm volatile("ldmatrix.sync.aligned.m8n8.x2.shared.b16 {%0,%1}, [%2];"
        : "=r"(a[0]), "=r"(a[1]) : "r"(addr));
}
__device__ __forceinline__ float cvt_tf32_f(float x) {
    uint32_t r;
    asm("cvt.rna.tf32.f32 %0, %1;" : "=r"(r) : "f"(x));
    return __uint_as_float(r);
}
__device__ __forceinline__ void mma_tf32(float c[4], const uint32_t a[4], const uint32_t b[2]) {
    asm volatile(
        "mma.sync.aligned.m16n8k8.row.col.f32.tf32.tf32.f32 "
        "{%0,%1,%2,%3}, {%4,%5,%6,%7}, {%8,%9}, {%0,%1,%2,%3};"
        : "+f"(c[0]), "+f"(c[1]), "+f"(c[2]), "+f"(c[3])
        : "r"(a[0]), "r"(a[1]), "r"(a[2]), "r"(a[3]), "r"(b[0]), "r"(b[1]));
}

// ---------------------------------------------------------------------------
// tf32 pre-round pass: out[i] = rna_tf32(in[i])  (idempotent)
// ---------------------------------------------------------------------------
__global__ void __launch_bounds__(256) cvt_tf32_copy(
    const float* __restrict__ in, float* __restrict__ out, int n4)
{
    int i = blockIdx.x * 256 + threadIdx.x;
    if (i < n4) {
        float4 v = reinterpret_cast<const float4*>(in)[i];
        v.x = cvt_tf32_f(v.x); v.y = cvt_tf32_f(v.y);
        v.z = cvt_tf32_f(v.z); v.w = cvt_tf32_f(v.w);
        reinterpret_cast<float4*>(out)[i] = v;
    }
}

// ---------------------------------------------------------------------------
// TF32 mma.sync GEMM: C[M,N] = A[M,K] @ B[N,K]^T + bias[N]
// Operands must be pre-rounded to tf32 bit patterns. No cvt in mainloop.
// ---------------------------------------------------------------------------
#define BKC 32
#define STAGE_BYTES 32768
#define GEMM_SMEM (3 * STAGE_BYTES)

__global__ void __launch_bounds__(256, 2) gemm_tf32(
    const float* __restrict__ A, const float* __restrict__ B,
    const float* __restrict__ bias, float* __restrict__ C,
    int M, int N, int K)
{
    extern __shared__ char smem[];
    const uint32_t sb = smem_u32(smem);
    const int tid  = threadIdx.x;
    const int lane = tid & 31;
    const int wid  = tid >> 5;
    const int row0 = blockIdx.y * 128;
    const int col0 = blockIdx.x * 128;
    const int wm = (wid >> 2) * 64;
    const int wn = (wid & 3) * 32;

    const int r = tid >> 3;
    const int c = tid & 7;
    const float* aSrc = A + (size_t)(row0 + r) * K + c * 4;
    const float* bSrc = B + (size_t)(col0 + r) * K + c * 4;
    uint32_t dOff[4];
    #pragma unroll
    for (int l = 0; l < 4; l++) {
        int row = r + 32 * l;
        dOff[l] = (uint32_t)(row * 128 + ((c * 16) ^ ((row & 7) << 4)));
    }

    const int nk = K / BKC;

    uint32_t aRow[4], bRow[4];
    #pragma unroll
    for (int mi = 0; mi < 4; mi++) aRow[mi] = (uint32_t)((wm + mi * 16 + (lane & 15)) * 128);
    #pragma unroll
    for (int ni = 0; ni < 4; ni++) bRow[ni] = (uint32_t)((wn + ni * 8 + (lane & 7)) * 128);
    const uint32_t xorv = (uint32_t)((lane & 7) << 4);
    const uint32_t aseg = (uint32_t)((lane >> 4) * 16);
    const uint32_t bseg = (uint32_t)(((lane >> 3) & 1) * 16);

    float acc[16][4];
    #pragma unroll
    for (int t = 0; t < 16; t++)
        #pragma unroll
        for (int j = 0; j < 4; j++) acc[t][j] = 0.f;

    #pragma unroll
    for (int p = 0; p < 2; p++) {
        uint32_t base = sb + p * STAGE_BYTES;
        size_t koff = (size_t)p * BKC;
        #pragma unroll
        for (int l = 0; l < 4; l++) CP16(base + dOff[l],         aSrc + (size_t)l * 32 * K + koff);
        #pragma unroll
        for (int l = 0; l < 4; l++) CP16(base + 16384 + dOff[l], bSrc + (size_t)l * 32 * K + koff);
        CP_COMMIT();
    }

    int sCur = 0, sNext = 2;
    for (int i = 0; i < nk; i++) {
        CP_WAIT1();
        __syncthreads();

        if (i + 2 < nk) {
            uint32_t base = sb + sNext * STAGE_BYTES;
            size_t koff = (size_t)(i + 2) * BKC;
            #pragma unroll
            for (int l = 0; l < 4; l++) CP16(base + dOff[l],         aSrc + (size_t)l * 32 * K + koff);
            #pragma unroll
            for (int l = 0; l < 4; l++) CP16(base + 16384 + dOff[l], bSrc + (size_t)l * 32 * K + koff);
        }
        CP_COMMIT();

        const uint32_t aBase = sb + sCur * STAGE_BYTES;
        const uint32_t bBase = aBase + 16384;

        #pragma unroll
        for (int ks = 0; ks < 4; ks++) {
            const uint32_t kb = (uint32_t)(ks * 32);
            uint32_t af[4][4], bf[4][2];
            #pragma unroll
            for (int mi = 0; mi < 4; mi++)
                ldsm_x4(af[mi], aBase + aRow[mi] + ((kb + aseg) ^ xorv));
            #pragma unroll
            for (int ni = 0; ni < 4; ni++)
                ldsm_x2(bf[ni], bBase + bRow[ni] + ((kb + bseg) ^ xorv));
            #pragma unroll
            for (int mi = 0; mi < 4; mi++)
                #pragma unroll
                for (int ni = 0; ni < 4; ni++)
                    mma_tf32(acc[mi * 4 + ni], af[mi], bf[ni]);
        }

        sCur = (sCur + 1) % 3;
        sNext = (sNext + 1) % 3;
    }

    const int gq = lane >> 2;
    const int qc = lane & 3;
    #pragma unroll
    for (int mi = 0; mi < 4; mi++) {
        #pragma unroll
        for (int ni = 0; ni < 4; ni++) {
            const float* ac = acc[mi * 4 + ni];
            int colb = col0 + wn + ni * 8 + qc * 2;
            float b0 = __ldg(&bias[colb]);
            float b1 = __ldg(&bias[colb + 1]);
            size_t base0 = (size_t)(row0 + wm + mi * 16 + gq) * N + colb;
            C[base0]         = ac[0] + b0;
            C[base0 + 1]     = ac[1] + b1;
            C[base0 + 8 * (size_t)N]     = ac[2] + b0;
            C[base0 + 8 * (size_t)N + 1] = ac[3] + b1;
        }
    }
}

// ---------------------------------------------------------------------------
// RoPE + transpose (unchanged)
// ---------------------------------------------------------------------------
__global__ void __launch_bounds__(256) rope_transpose(
    const float* __restrict__ qkv, const float* __restrict__ rope,
    float* __restrict__ q, float* __restrict__ k, float* __restrict__ v)
{
    int idx = blockIdx.x * 256 + threadIdx.x;
    int d = idx & 63;
    int h = (idx >> 6) & 31;
    int t = (idx >> 11) & 1023;
    int b = idx >> 21;

    const float* row = qkv + (size_t)(b * SEQ + t) * QKVN;
    int col = h * HDIM + d;

    float qv, kv;
    if (d < 32) {
        int j = d & 15;
        float cs = rope[(t * 16 + j) * 2 + 0];
        float sn = rope[(t * 16 + j) * 2 + 1];
        if (d < 16) {
            qv = row[col]        * cs - row[col + 16]        * sn;
            kv = row[CDIM + col] * cs - row[CDIM + col + 16] * sn;
        } else {
            qv = row[col]        * cs + row[col - 16]        * sn;
            kv = row[CDIM + col] * cs + row[CDIM + col - 16] * sn;
        }
    } else {
        qv = row[col];
        kv = row[CDIM + col];
    }
    float vv = row[2 * CDIM + col];

    size_t o = ((size_t)(b * NHEAD + h) * SEQ + t) * HDIM + d;
    q[o] = qv; k[o] = kv; v[o] = vv;
}

// ---------------------------------------------------------------------------
// Causal flash attention, fp32 scalar (ctx stores tf32-rounded).
// ---------------------------------------------------------------------------
#define ATTN_SMEM (4 * 64 * 65 * 4)   // 66560

__global__ void __launch_bounds__(256) attn_kernel(
    const float* __restrict__ Q, const float* __restrict__ K,
    const float* __restrict__ V, float* __restrict__ ctx)
{
    extern __shared__ float sm[];
    float (*qs)[65] = (float(*)[65])(sm);
    float (*ks)[65] = (float(*)[65])(sm + 64 * 65);
    float (*vs)[65] = (float(*)[65])(sm + 2 * 64 * 65);
    float (*ps)[65] = (float(*)[65])(sm + 3 * 64 * 65);

    const int bh = blockIdx.y;
    const int b  = bh >> 5;
    const int h  = bh & 31;
    const int qt = blockIdx.x;
    const int q0 = qt * 64;
    const int tid = threadIdx.x;
    const int rg = tid >> 4;
    const int cg = tid & 15;

    const float* Qb = Q + ((size_t)bh * SEQ + q0) * HDIM;
    #pragma unroll
    for (int l2 = 0; l2 < 4; l2++) {
        int id = tid + l2 * 256;
        int r  = id >> 4;
        int c4 = (id & 15) << 2;
        float4 v4 = *reinterpret_cast<const float4*>(Qb + r * HDIM + c4);
        qs[r][c4] = v4.x; qs[r][c4 + 1] = v4.y; qs[r][c4 + 2] = v4.z; qs[r][c4 + 3] = v4.w;
    }

    float acc[4][4];
    float mrow[4], lrow[4];
    #pragma unroll
    for (int i = 0; i < 4; i++) {
        mrow[i] = -1e30f; lrow[i] = 0.f;
        #pragma unroll
        for (int j = 0; j < 4; j++) acc[i][j] = 0.f;
    }
    const float scale = 0.125f;

    for (int kt = 0; kt <= qt; kt++) {
        const int k0 = kt * 64;
        const float* Kb = K + ((size_t)bh * SEQ + k0) * HDIM;
        const float* Vb = V + ((size_t)bh * SEQ + k0) * HDIM;

        __syncthreads();
        #pragma unroll
        for (int l2 = 0; l2 < 4; l2++) {
            int id = tid + l2 * 256;
            int r  = id >> 4;
            int c4 = (id & 15) << 2;
            float4 k4 = *reinterpret_cast<const float4*>(Kb + r * HDIM + c4);
            ks[r][c4] = k4.x; ks[r][c4 + 1] = k4.y; ks[r][c4 + 2] = k4.z; ks[r][c4 + 3] = k4.w;
            float4 v4 = *reinterpret_cast<const float4*>(Vb + r * HDIM + c4);
            vs[r][c4] = v4.x; vs[r][c4 + 1] = v4.y; vs[r][c4 + 2] = v4.z; vs[r][c4 + 3] = v4.w;
        }
        __syncthreads();

        float s[4][4];
        #pragma unroll
        for (int i = 0; i < 4; i++)
            #pragma unroll
            for (int j = 0; j < 4; j++) s[i][j] = 0.f;

        #pragma unroll 8
        for (int d = 0; d < 64; d++) {
            float qv[4], kv[4];
            #pragma unroll
            for (int i = 0; i < 4; i++) qv[i] = qs[rg * 4 + i][d];
            #pragma unroll
            for (int j = 0; j < 4; j++) kv[j] = ks[cg * 4 + j][d];
            #pragma unroll
            for (int i = 0; i < 4; i++)
                #pragma unroll
                for (int j = 0; j < 4; j++)
                    s[i][j] += qv[i] * kv[j];
        }

        const bool diag = (kt == qt);
        #pragma unroll
        for (int i = 0; i < 4; i++)
            #pragma unroll
            for (int j = 0; j < 4; j++) {
                float val = s[i][j] * scale;
                if (diag && (k0 + cg * 4 + j > q0 + rg * 4 + i)) val = -1e30f;
                s[i][j] = val;
            }

        #pragma unroll
        for (int i = 0; i < 4; i++) {
            float mx = s[i][0];
            #pragma unroll
            for (int j = 1; j < 4; j++) mx = fmaxf(mx, s[i][j]);
            #pragma unroll
            for (int off = 8; off; off >>= 1)
                mx = fmaxf(mx, __shfl_xor_sync(0xffffffffu, mx, off));

            float mn   = fmaxf(mrow[i], mx);
            float corr = __expf(mrow[i] - mn);
            float rs   = 0.f;
            float p[4];
            #pragma unroll
            for (int j = 0; j < 4; j++) { p[j] = __expf(s[i][j] - mn); rs += p[j]; }
            #pragma unroll
            for (int off = 8; off; off >>= 1)
                rs += __shfl_xor_sync(0xffffffffu, rs, off);

            lrow[i] = lrow[i] * corr + rs;
            mrow[i] = mn;
            #pragma unroll
            for (int j = 0; j < 4; j++) acc[i][j] *= corr;
            #pragma unroll
            for (int j = 0; j < 4; j++) ps[rg * 4 + i][cg * 4 + j] = p[j];
        }
        __syncthreads();

        #pragma unroll 8
        for (int cc = 0; cc < 64; cc++) {
            float pv[4], vv[4];
            #pragma unroll
            for (int i = 0; i < 4; i++) pv[i] = ps[rg * 4 + i][cc];
            #pragma unroll
            for (int j = 0; j < 4; j++) vv[j] = vs[cc][cg * 4 + j];
            #pragma unroll
            for (int i = 0; i < 4; i++)
                #pragma unroll
                for (int j = 0; j < 4; j++)
                    acc[i][j] += pv[i] * vv[j];
        }
    }

    // ctx is consumed only as GEMM-A: store tf32-pre-rounded values
    #pragma unroll
    for (int i = 0; i < 4; i++) {
        int t = q0 + rg * 4 + i;
        float inv = 1.f / lrow[i];
        size_t base = ((size_t)b * SEQ + t) * CDIM + h * HDIM + cg * 4;
        #pragma unroll
        for (int j = 0; j < 4; j++)
            ctx[base + j] = cvt_tf32_f(acc[i][j] * inv);
    }
}

// ---------------------------------------------------------------------------
extern "C" void kernel_launch(void* const* d_in, const int* in_sizes, int n_in,
                              void* d_out, int out_size)
{
    const float* x      = (const float*)d_in[0];
    const float* rope   = (const float*)d_in[3];
    const float* Wqkv_w = (const float*)d_in[4];
    const float* Wqkv_b = (const float*)d_in[5];
    const float* out_w  = (const float*)d_in[6];
    const float* out_b  = (const float*)d_in[7];
    float* out = (float*)d_out;

    float *qkv, *q, *k, *v, *xc, *w1, *w2;
    cudaGetSymbolAddress((void**)&qkv, g_qkv);
    cudaGetSymbolAddress((void**)&q,   g_q);
    cudaGetSymbolAddress((void**)&k,   g_k);
    cudaGetSymbolAddress((void**)&v,   g_v);
    cudaGetSymbolAddress((void**)&xc,  g_xc);
    cudaGetSymbolAddress((void**)&w1,  g_w1);
    cudaGetSymbolAddress((void**)&w2,  g_w2);
    float* ctx = qkv;

    // max smem carveout so 2 GEMM CTAs / 2-3 attn CTAs co-reside per SM
    cudaFuncSetAttribute(gemm_tf32, cudaFuncAttributeMaxDynamicSharedMemorySize, GEMM_SMEM);
    cudaFuncSetAttribute(gemm_tf32, cudaFuncAttributePreferredSharedMemoryCarveout, 100);
    cudaFuncSetAttribute(attn_kernel, cudaFuncAttributeMaxDynamicSharedMemorySize, ATTN_SMEM);
    cudaFuncSetAttribute(attn_kernel, cudaFuncAttributePreferredSharedMemoryCarveout, 100);

    // 0) pre-round GEMM operands to tf32 bit patterns
    cvt_tf32_copy<<<(MROWS * CDIM / 4 + 255) / 256, 256>>>(x,      xc, MROWS * CDIM / 4);
    cvt_tf32_copy<<<(QKVN  * CDIM / 4 + 255) / 256, 256>>>(Wqkv_w, w1, QKVN  * CDIM / 4);
    cvt_tf32_copy<<<(CDIM  * CDIM / 4 + 255) / 256, 256>>>(out_w,  w2, CDIM  * CDIM / 4);

    // 1) QKV projection (tf32 tensor cores, no mainloop cvt)
    gemm_tf32<<<dim3(QKVN / 128, MROWS / 128), 256, GEMM_SMEM>>>(
        xc, w1, Wqkv_b, qkv, MROWS, QKVN, CDIM);

    // 2) RoPE + transpose
    rope_transpose<<<(BATCH * SEQ * NHEAD * HDIM) / 256, 256>>>(qkv, rope, q, k, v);

    // 3) causal attention (fp32 scalar, ctx pre-rounded on store)
    attn_kernel<<<dim3(SEQ / 64, BATCH * NHEAD), 256, ATTN_SMEM>>>(q, k, v, ctx);

    // 4) output projection (tf32 tensor cores)
    gemm_tf32<<<dim3(CDIM / 128, MROWS / 128), 256, GEMM_SMEM>>>(
        ctx, w2, out_b, out, MROWS, CDIM, CDIM);
}

// round 8
// speedup vs baseline: 1.6501x; 1.4371x over previous
#include <cuda_runtime.h>
#include <cuda_bf16.h>
#include <cstdint>

// Problem constants
#define BATCH 4
#define SEQ   1024
#define CDIM  2048
#define NHEAD 32
#define HDIM  64
#define QKVN  (3*CDIM)          // 6144
#define MROWS (BATCH*SEQ)       // 4096

// Scratch (device globals: allocation-free rule)
__device__ float g_qkv[(size_t)MROWS * QKVN];
__device__ float g_q[(size_t)BATCH*NHEAD*SEQ*HDIM];
__device__ float g_k[(size_t)BATCH*NHEAD*SEQ*HDIM];
__device__ float g_v[(size_t)BATCH*NHEAD*SEQ*HDIM];
// tf32-pre-rounded operand copies
__device__ float g_xc[(size_t)MROWS * CDIM];
__device__ float g_w1[(size_t)QKVN * CDIM];
__device__ float g_w2[(size_t)CDIM * CDIM];

// ---------------------------------------------------------------------------
// helpers
// ---------------------------------------------------------------------------
__device__ __forceinline__ uint32_t smem_u32(const void* p) {
    uint32_t a;
    asm("{ .reg .u64 t; cvta.to.shared.u64 t, %1; cvt.u32.u64 %0, t; }" : "=r"(a) : "l"(p));
    return a;
}
#define CP16(dst, src) \
    asm volatile("cp.async.cg.shared.global [%0], [%1], 16;" :: "r"(dst), "l"(src) : "memory")
#define CP_COMMIT() asm volatile("cp.async.commit_group;" ::: "memory")
#define CP_WAIT1()  asm volatile("cp.async.wait_group 1;" ::: "memory")
#define CP_WAIT0()  asm volatile("cp.async.wait_group 0;" ::: "memory")

__device__ __forceinline__ void ldsm_x4(uint32_t a[4], uint32_t addr) {
    asm volatile("ldmatrix.sync.aligned.m8n8.x4.shared.b16 {%0,%1,%2,%3}, [%4];"
        : "=r"(a[0]), "=r"(a[1]), "=r"(a[2]), "=r"(a[3]) : "r"(addr));
}
__device__ __forceinline__ void ldsm_x2(uint32_t a[2], uint32_t addr) {
    asm volatile("ldmatrix.sync.aligned.m8n8.x2.shared.b16 {%0,%1}, [%2];"
        : "=r"(a[0]), "=r"(a[1]) : "r"(addr));
}
__device__ __forceinline__ float cvt_tf32_f(float x) {
    uint32_t r;
    asm("cvt.rna.tf32.f32 %0, %1;" : "=r"(r) : "f"(x));
    return __uint_as_float(r);
}
__device__ __forceinline__ void mma_tf32(float c[4], const uint32_t a[4], const uint32_t b[2]) {
    asm volatile(
        "mma.sync.aligned.m16n8k8.row.col.f32.tf32.tf32.f32 "
        "{%0,%1,%2,%3}, {%4,%5,%6,%7}, {%8,%9}, {%0,%1,%2,%3};"
        : "+f"(c[0]), "+f"(c[1]), "+f"(c[2]), "+f"(c[3])
        : "r"(a[0]), "r"(a[1]), "r"(a[2]), "r"(a[3]), "r"(b[0]), "r"(b[1]));
}

// ---------------------------------------------------------------------------
// tf32 pre-round pass: out[i] = rna_tf32(in[i])  (idempotent)
// ---------------------------------------------------------------------------
__global__ void __launch_bounds__(256) cvt_tf32_copy(
    const float* __restrict__ in, float* __restrict__ out, int n4)
{
    int i = blockIdx.x * 256 + threadIdx.x;
    if (i < n4) {
        float4 v = reinterpret_cast<const float4*>(in)[i];
        v.x = cvt_tf32_f(v.x); v.y = cvt_tf32_f(v.y);
        v.z = cvt_tf32_f(v.z); v.w = cvt_tf32_f(v.w);
        reinterpret_cast<float4*>(out)[i] = v;
    }
}

// ---------------------------------------------------------------------------
// TF32 mma.sync GEMM: C[M,N] = A[M,K] @ B[N,K]^T + bias[N]  (unchanged)
// ---------------------------------------------------------------------------
#define BKC 32
#define STAGE_BYTES 32768
#define GEMM_SMEM (3 * STAGE_BYTES)

__global__ void __launch_bounds__(256, 2) gemm_tf32(
    const float* __restrict__ A, const float* __restrict__ B,
    const float* __restrict__ bias, float* __restrict__ C,
    int M, int N, int K)
{
    extern __shared__ char smem[];
    const uint32_t sb = smem_u32(smem);
    const int tid  = threadIdx.x;
    const int lane = tid & 31;
    const int wid  = tid >> 5;
    const int row0 = blockIdx.y * 128;
    const int col0 = blockIdx.x * 128;
    const int wm = (wid >> 2) * 64;
    const int wn = (wid & 3) * 32;

    const int r = tid >> 3;
    const int c = tid & 7;
    const float* aSrc = A + (size_t)(row0 + r) * K + c * 4;
    const float* bSrc = B + (size_t)(col0 + r) * K + c * 4;
    uint32_t dOff[4];
    #pragma unroll
    for (int l = 0; l < 4; l++) {
        int row = r + 32 * l;
        dOff[l] = (uint32_t)(row * 128 + ((c * 16) ^ ((row & 7) << 4)));
    }

    const int nk = K / BKC;

    uint32_t aRow[4], bRow[4];
    #pragma unroll
    for (int mi = 0; mi < 4; mi++) aRow[mi] = (uint32_t)((wm + mi * 16 + (lane & 15)) * 128);
    #pragma unroll
    for (int ni = 0; ni < 4; ni++) bRow[ni] = (uint32_t)((wn + ni * 8 + (lane & 7)) * 128);
    const uint32_t xorv = (uint32_t)((lane & 7) << 4);
    const uint32_t aseg = (uint32_t)((lane >> 4) * 16);
    const uint32_t bseg = (uint32_t)(((lane >> 3) & 1) * 16);

    float acc[16][4];
    #pragma unroll
    for (int t = 0; t < 16; t++)
        #pragma unroll
        for (int j = 0; j < 4; j++) acc[t][j] = 0.f;

    #pragma unroll
    for (int p = 0; p < 2; p++) {
        uint32_t base = sb + p * STAGE_BYTES;
        size_t koff = (size_t)p * BKC;
        #pragma unroll
        for (int l = 0; l < 4; l++) CP16(base + dOff[l],         aSrc + (size_t)l * 32 * K + koff);
        #pragma unroll
        for (int l = 0; l < 4; l++) CP16(base + 16384 + dOff[l], bSrc + (size_t)l * 32 * K + koff);
        CP_COMMIT();
    }

    int sCur = 0, sNext = 2;
    for (int i = 0; i < nk; i++) {
        CP_WAIT1();
        __syncthreads();

        if (i + 2 < nk) {
            uint32_t base = sb + sNext * STAGE_BYTES;
            size_t koff = (size_t)(i + 2) * BKC;
            #pragma unroll
            for (int l = 0; l < 4; l++) CP16(base + dOff[l],         aSrc + (size_t)l * 32 * K + koff);
            #pragma unroll
            for (int l = 0; l < 4; l++) CP16(base + 16384 + dOff[l], bSrc + (size_t)l * 32 * K + koff);
        }
        CP_COMMIT();

        const uint32_t aBase = sb + sCur * STAGE_BYTES;
        const uint32_t bBase = aBase + 16384;

        #pragma unroll
        for (int ks = 0; ks < 4; ks++) {
            const uint32_t kb = (uint32_t)(ks * 32);
            uint32_t af[4][4], bf[4][2];
            #pragma unroll
            for (int mi = 0; mi < 4; mi++)
                ldsm_x4(af[mi], aBase + aRow[mi] + ((kb + aseg) ^ xorv));
            #pragma unroll
            for (int ni = 0; ni < 4; ni++)
                ldsm_x2(bf[ni], bBase + bRow[ni] + ((kb + bseg) ^ xorv));
            #pragma unroll
            for (int mi = 0; mi < 4; mi++)
                #pragma unroll
                for (int ni = 0; ni < 4; ni++)
                    mma_tf32(acc[mi * 4 + ni], af[mi], bf[ni]);
        }

        sCur = (sCur + 1) % 3;
        sNext = (sNext + 1) % 3;
    }

    const int gq = lane >> 2;
    const int qc = lane & 3;
    #pragma unroll
    for (int mi = 0; mi < 4; mi++) {
        #pragma unroll
        for (int ni = 0; ni < 4; ni++) {
            const float* ac = acc[mi * 4 + ni];
            int colb = col0 + wn + ni * 8 + qc * 2;
            float b0 = __ldg(&bias[colb]);
            float b1 = __ldg(&bias[colb + 1]);
            size_t base0 = (size_t)(row0 + wm + mi * 16 + gq) * N + colb;
            C[base0]         = ac[0] + b0;
            C[base0 + 1]     = ac[1] + b1;
            C[base0 + 8 * (size_t)N]     = ac[2] + b0;
            C[base0 + 8 * (size_t)N + 1] = ac[3] + b1;
        }
    }
}

// ---------------------------------------------------------------------------
// RoPE + transpose; q/k/v stored tf32-RNA-rounded (they feed tensor-core attn)
// ---------------------------------------------------------------------------
__global__ void __launch_bounds__(256) rope_transpose(
    const float* __restrict__ qkv, const float* __restrict__ rope,
    float* __restrict__ q, float* __restrict__ k, float* __restrict__ v)
{
    int idx = blockIdx.x * 256 + threadIdx.x;
    int d = idx & 63;
    int h = (idx >> 6) & 31;
    int t = (idx >> 11) & 1023;
    int b = idx >> 21;

    const float* row = qkv + (size_t)(b * SEQ + t) * QKVN;
    int col = h * HDIM + d;

    float qv, kv;
    if (d < 32) {
        int j = d & 15;
        float cs = rope[(t * 16 + j) * 2 + 0];
        float sn = rope[(t * 16 + j) * 2 + 1];
        if (d < 16) {
            qv = row[col]        * cs - row[col + 16]        * sn;
            kv = row[CDIM + col] * cs - row[CDIM + col + 16] * sn;
        } else {
            qv = row[col]        * cs + row[col - 16]        * sn;
            kv = row[CDIM + col] * cs + row[CDIM + col - 16] * sn;
        }
    } else {
        qv = row[col];
        kv = row[CDIM + col];
    }
    float vv = row[2 * CDIM + col];

    size_t o = ((size_t)(b * NHEAD + h) * SEQ + t) * HDIM + d;
    q[o] = cvt_tf32_f(qv); k[o] = cvt_tf32_f(kv); v[o] = cvt_tf32_f(vv);
}

// ---------------------------------------------------------------------------
// Tensor-core causal flash attention (tf32 mma.sync).
// Block: 128 q-rows, 8 warps (one m16 band each, full 64 cols); K tiles of 64.
// smem: qs(32K) ks(16K) vsT(16K) ps(32K) = 96KB, GEMM-style SW128 panels.
// ---------------------------------------------------------------------------
#define ATTN_SMEM2 98304
#define OFF_QS 0u
#define OFF_KS 32768u
#define OFF_VT 49152u
#define OFF_PS 65536u

__global__ void __launch_bounds__(256) attn_tc(
    const float* __restrict__ Q, const float* __restrict__ K,
    const float* __restrict__ V, float* __restrict__ ctx)
{
    extern __shared__ char smem[];
    const uint32_t sb = smem_u32(smem);
    const int tid  = threadIdx.x;
    const int lane = tid & 31;
    const int wid  = tid >> 5;
    const int bh   = blockIdx.y;
    const int b    = bh >> 5;
    const int h    = bh & 31;
    const int qt   = blockIdx.x;
    const int q0   = qt * 128;

    // ---- stage Q tile (128 x 64) into 2 swizzled panels ----
    const float* Qg = Q + ((size_t)bh * SEQ + q0) * HDIM;
    #pragma unroll
    for (int l = 0; l < 8; l++) {
        int id  = tid + l * 256;          // 0..2047
        int row = id >> 4;
        int d4  = id & 15;
        uint32_t dst = sb + OFF_QS + (uint32_t)((d4 >> 3) * 16384 + row * 128
                        + (((d4 & 7) * 16) ^ ((row & 7) << 4)));
        CP16(dst, Qg + row * HDIM + d4 * 4);
    }
    CP_COMMIT();

    // fragment addressing (identical scheme to gemm_tf32)
    const uint32_t aRow = (uint32_t)((wid * 16 + (lane & 15)) * 128);
    const uint32_t bRowB = (uint32_t)((lane & 7) * 128);
    const uint32_t xorv = (uint32_t)((lane & 7) << 4);
    const uint32_t aseg = (uint32_t)((lane >> 4) * 16);
    const uint32_t bseg = (uint32_t)(((lane >> 3) & 1) * 16);
    const int gq = lane >> 2;
    const int qc = lane & 3;

    float o[8][4];
    #pragma unroll
    for (int ni = 0; ni < 8; ni++)
        #pragma unroll
        for (int e = 0; e < 4; e++) o[ni][e] = 0.f;
    float m0 = -1e30f, m1 = -1e30f, l0 = 0.f, l1 = 0.f;

    const int rowmin = q0 + wid * 16;       // warp's smallest q row
    const int rowmax = rowmin + 15;         // warp's largest q row
    const int r0g = rowmin + gq;
    const int r1g = r0g + 8;
    const int nkt = 2 * qt + 2;
    const float scale = 0.125f;

    for (int kt = 0; kt < nkt; kt++) {
        const int k0 = kt * 64;
        __syncthreads();   // prior tile's ks/vsT reads complete

        // stage K tile (64 x 64) via cp.async
        const float* Kg = K + ((size_t)bh * SEQ + k0) * HDIM;
        #pragma unroll
        for (int l = 0; l < 4; l++) {
            int id = tid + l * 256;       // 0..1023
            int kk = id >> 4;
            int d4 = id & 15;
            uint32_t dst = sb + OFF_KS + (uint32_t)((d4 >> 3) * 8192 + kk * 128
                            + (((d4 & 7) * 16) ^ ((kk & 7) << 4)));
            CP16(dst, Kg + kk * HDIM + d4 * 4);
        }
        CP_COMMIT();

        // stage V^T (d-major) with scalar stores
        const float* Vg = V + ((size_t)bh * SEQ + k0) * HDIM;
        #pragma unroll
        for (int l = 0; l < 4; l++) {
            int id = tid + l * 256;
            int kk = id >> 4;
            int d4 = id & 15;
            float4 vv = *reinterpret_cast<const float4*>(Vg + kk * HDIM + d4 * 4);
            #pragma unroll
            for (int i = 0; i < 4; i++) {
                int dd = d4 * 4 + i;
                uint32_t adr = sb + OFF_VT + (uint32_t)((kk >> 5) * 8192 + dd * 128
                                + (((kk & 31) * 4) ^ ((dd & 7) << 4)));
                float fv = (i == 0) ? vv.x : (i == 1) ? vv.y : (i == 2) ? vv.z : vv.w;
                asm volatile("st.shared.f32 [%0], %1;" :: "r"(adr), "f"(fv) : "memory");
            }
        }
        CP_WAIT0();
        __syncthreads();

        if (k0 <= rowmax) {
            // ---- S = Q @ K^T ----
            float s[8][4];
            #pragma unroll
            for (int ni = 0; ni < 8; ni++)
                #pragma unroll
                for (int e = 0; e < 4; e++) s[ni][e] = 0.f;

            #pragma unroll
            for (int pn = 0; pn < 2; pn++) {
                const uint32_t qb = sb + OFF_QS + pn * 16384u;
                const uint32_t kb_ = sb + OFF_KS + pn * 8192u;
                #pragma unroll
                for (int k8 = 0; k8 < 4; k8++) {
                    const uint32_t kb = (uint32_t)(k8 * 32);
                    uint32_t af[4];
                    ldsm_x4(af, qb + aRow + ((kb + aseg) ^ xorv));
                    #pragma unroll
                    for (int ni = 0; ni < 8; ni++) {
                        uint32_t bf[2];
                        ldsm_x2(bf, kb_ + bRowB + ni * 1024u + ((kb + bseg) ^ xorv));
                        mma_tf32(s[ni], af, bf);
                    }
                }
            }

            // ---- scale + causal mask ----
            // BUGFIX vs R7: mask is needed whenever the tile extends past the
            // warp's SMALLEST row (rowmin), not its largest.
            const bool need_mask = (k0 + 63 > rowmin);
            #pragma unroll
            for (int ni = 0; ni < 8; ni++) {
                int c0 = k0 + ni * 8 + qc * 2;
                if (need_mask) {
                    s[ni][0] = (c0     > r0g) ? -1e30f : s[ni][0] * scale;
                    s[ni][1] = (c0 + 1 > r0g) ? -1e30f : s[ni][1] * scale;
                    s[ni][2] = (c0     > r1g) ? -1e30f : s[ni][2] * scale;
                    s[ni][3] = (c0 + 1 > r1g) ? -1e30f : s[ni][3] * scale;
                } else {
                    s[ni][0] *= scale; s[ni][1] *= scale;
                    s[ni][2] *= scale; s[ni][3] *= scale;
                }
            }

            // ---- online softmax on fragments ----
            float mx0 = -1e30f, mx1 = -1e30f;
            #pragma unroll
            for (int ni = 0; ni < 8; ni++) {
                mx0 = fmaxf(mx0, fmaxf(s[ni][0], s[ni][1]));
                mx1 = fmaxf(mx1, fmaxf(s[ni][2], s[ni][3]));
            }
            mx0 = fmaxf(mx0, __shfl_xor_sync(0xffffffffu, mx0, 1));
            mx0 = fmaxf(mx0, __shfl_xor_sync(0xffffffffu, mx0, 2));
            mx1 = fmaxf(mx1, __shfl_xor_sync(0xffffffffu, mx1, 1));
            mx1 = fmaxf(mx1, __shfl_xor_sync(0xffffffffu, mx1, 2));

            const float mn0 = fmaxf(m0, mx0);
            const float mn1 = fmaxf(m1, mx1);
            const float corr0 = __expf(m0 - mn0);
            const float corr1 = __expf(m1 - mn1);

            float rs0 = 0.f, rs1 = 0.f;
            const int prow0 = wid * 16 + gq;
            #pragma unroll
            for (int ni = 0; ni < 8; ni++) {
                float p0 = __expf(s[ni][0] - mn0);
                float p1 = __expf(s[ni][1] - mn0);
                float p2 = __expf(s[ni][2] - mn1);
                float p3 = __expf(s[ni][3] - mn1);
                rs0 += p0 + p1;
                rs1 += p2 + p3;
                // store P (tf32-rounded) into ps tile, GEMM-A layout
                int col = ni * 8 + qc * 2;
                uint32_t pa = sb + OFF_PS + (uint32_t)((col >> 5) * 16384
                               + prow0 * 128 + (((col & 31) * 4) ^ ((gq & 7) << 4)));
                asm volatile("st.shared.v2.f32 [%0], {%1,%2};"
                    :: "r"(pa), "f"(cvt_tf32_f(p0)), "f"(cvt_tf32_f(p1)) : "memory");
                asm volatile("st.shared.v2.f32 [%0], {%1,%2};"
                    :: "r"(pa + 8 * 128), "f"(cvt_tf32_f(p2)), "f"(cvt_tf32_f(p3)) : "memory");
            }
            rs0 += __shfl_xor_sync(0xffffffffu, rs0, 1);
            rs0 += __shfl_xor_sync(0xffffffffu, rs0, 2);
            rs1 += __shfl_xor_sync(0xffffffffu, rs1, 1);
            rs1 += __shfl_xor_sync(0xffffffffu, rs1, 2);

            l0 = l0 * corr0 + rs0;
            l1 = l1 * corr1 + rs1;
            m0 = mn0; m1 = mn1;

            #pragma unroll
            for (int ni = 0; ni < 8; ni++) {
                o[ni][0] *= corr0; o[ni][1] *= corr0;
                o[ni][2] *= corr1; o[ni][3] *= corr1;
            }
            __syncwarp();   // P stores visible to warp's ldmatrix

            // ---- O += P @ V ----
            #pragma unroll
            for (int pn = 0; pn < 2; pn++) {
                const uint32_t pb = sb + OFF_PS + pn * 16384u;
                const uint32_t vb = sb + OFF_VT + pn * 8192u;
                #pragma unroll
                for (int k8 = 0; k8 < 4; k8++) {
                    const uint32_t kb = (uint32_t)(k8 * 32);
                    uint32_t af[4];
                    ldsm_x4(af, pb + aRow + ((kb + aseg) ^ xorv));
                    #pragma unroll
                    for (int ni = 0; ni < 8; ni++) {
                        uint32_t bf[2];
                        ldsm_x2(bf, vb + bRowB + ni * 1024u + ((kb + bseg) ^ xorv));
                        mma_tf32(o[ni], af, bf);
                    }
                }
            }
        }
    }

    // ---- epilogue: ctx[b, t, h*64+d], tf32-rounded (feeds out-proj GEMM) ----
    const float inv0 = 1.f / l0;
    const float inv1 = 1.f / l1;
    const int t0 = q0 + wid * 16 + gq;
    float* c0p = ctx + ((size_t)b * SEQ + t0) * CDIM + h * HDIM;
    float* c1p = c0p + 8 * (size_t)CDIM;
    #pragma unroll
    for (int ni = 0; ni < 8; ni++) {
        int d = ni * 8 + qc * 2;
        float2 w0 = make_float2(cvt_tf32_f(o[ni][0] * inv0), cvt_tf32_f(o[ni][1] * inv0));
        float2 w1 = make_float2(cvt_tf32_f(o[ni][2] * inv1), cvt_tf32_f(o[ni][3] * inv1));
        *reinterpret_cast<float2*>(c0p + d) = w0;
        *reinterpret_cast<float2*>(c1p + d) = w1;
    }
}

// ---------------------------------------------------------------------------
extern "C" void kernel_launch(void* const* d_in, const int* in_sizes, int n_in,
                              void* d_out, int out_size)
{
    const float* x      = (const float*)d_in[0];
    const float* rope   = (const float*)d_in[3];
    const float* Wqkv_w = (const float*)d_in[4];
    const float* Wqkv_b = (const float*)d_in[5];
    const float* out_w  = (const float*)d_in[6];
    const float* out_b  = (const float*)d_in[7];
    float* out = (float*)d_out;

    float *qkv, *q, *k, *v, *xc, *w1, *w2;
    cudaGetSymbolAddress((void**)&qkv, g_qkv);
    cudaGetSymbolAddress((void**)&q,   g_q);
    cudaGetSymbolAddress((void**)&k,   g_k);
    cudaGetSymbolAddress((void**)&v,   g_v);
    cudaGetSymbolAddress((void**)&xc,  g_xc);
    cudaGetSymbolAddress((void**)&w1,  g_w1);
    cudaGetSymbolAddress((void**)&w2,  g_w2);
    float* ctx = qkv;

    cudaFuncSetAttribute(gemm_tf32, cudaFuncAttributeMaxDynamicSharedMemorySize, GEMM_SMEM);
    cudaFuncSetAttribute(gemm_tf32, cudaFuncAttributePreferredSharedMemoryCarveout, 100);
    cudaFuncSetAttribute(attn_tc, cudaFuncAttributeMaxDynamicSharedMemorySize, ATTN_SMEM2);
    cudaFuncSetAttribute(attn_tc, cudaFuncAttributePreferredSharedMemoryCarveout, 100);

    // 0) pre-round GEMM operands to tf32 bit patterns
    cvt_tf32_copy<<<(MROWS * CDIM / 4 + 255) / 256, 256>>>(x,      xc, MROWS * CDIM / 4);
    cvt_tf32_copy<<<(QKVN  * CDIM / 4 + 255) / 256, 256>>>(Wqkv_w, w1, QKVN  * CDIM / 4);
    cvt_tf32_copy<<<(CDIM  * CDIM / 4 + 255) / 256, 256>>>(out_w,  w2, CDIM  * CDIM / 4);

    // 1) QKV projection (tf32 tensor cores)
    gemm_tf32<<<dim3(QKVN / 128, MROWS / 128), 256, GEMM_SMEM>>>(
        xc, w1, Wqkv_b, qkv, MROWS, QKVN, CDIM);

    // 2) RoPE + transpose (q/k/v tf32-rounded)
    rope_transpose<<<(BATCH * SEQ * NHEAD * HDIM) / 256, 256>>>(qkv, rope, q, k, v);

    // 3) causal attention on tensor cores
    attn_tc<<<dim3(SEQ / 128, BATCH * NHEAD), 256, ATTN_SMEM2>>>(q, k, v, ctx);

    // 4) output projection (tf32 tensor cores)
    gemm_tf32<<<dim3(CDIM / 128, MROWS / 128), 256, GEMM_SMEM>>>(
        ctx, w2, out_b, out, MROWS, CDIM, CDIM);
}